// round 1
// baseline (speedup 1.0000x reference)
#include <cuda_runtime.h>
#include <cuda_bf16.h>
#include <math.h>

// Problem constants
#define BATCH 4096
#define EMB 256
#define HID 256
#define GRP 8
#define FREQ 96
#define CHAN 16
#define OC 10
#define KT 5

// Output slab offsets (floats), concatenated: coefs, alpha, new_state, new_buf
#define OFF_COEFS 0
#define N_COEFS   (BATCH * 5 * 96 * 2)          // 3,932,160
#define OFF_ALPHA (N_COEFS)                      // 3,932,160
#define N_ALPHA   (BATCH)                        // 4,096
#define OFF_STATE (OFF_ALPHA + N_ALPHA)          // 3,936,256
#define N_STATE   (BATCH * 2 * HID)              // 2,097,152
#define OFF_BUF   (OFF_STATE + N_STATE)          // 6,033,408
#define N_BUF     (BATCH * 4 * FREQ * CHAN)      // 25,165,824

// Scratch (device globals; no runtime allocation)
__device__ float g_xin[BATCH * HID];
__device__ float g_c[BATCH * HID];

// ---------------------------------------------------------------------------
// x_in = relu(grouped_linear(emb, w_in))  [B,256] x (8 groups of 32x32)
// Block: 8 batch rows, 256 threads (one per output col).
// ---------------------------------------------------------------------------
__global__ __launch_bounds__(256) void xin_kernel(
    const float* __restrict__ emb, const float* __restrict__ w_in,
    float* __restrict__ xout)
{
    __shared__ float sE[8][EMB];
    int b0 = blockIdx.x * 8;
    int tid = threadIdx.x;
    for (int idx = tid; idx < 8 * EMB; idx += 256) {
        int r = idx >> 8, col = idx & 255;
        sE[r][col] = emb[(b0 + r) * EMB + col];
    }
    __syncthreads();
    int j = tid;
    int g = j >> 5, jo = j & 31;
    float acc[8] = {0.f,0.f,0.f,0.f,0.f,0.f,0.f,0.f};
    const float* w = w_in + g * (32 * 32) + jo;
    #pragma unroll 8
    for (int i = 0; i < 32; i++) {
        float wv = w[i * 32];
        #pragma unroll
        for (int r = 0; r < 8; r++)
            acc[r] = fmaf(sE[r][(g << 5) + i], wv, acc[r]);
    }
    #pragma unroll
    for (int r = 0; r < 8; r++)
        xout[(b0 + r) * HID + j] = fmaxf(acc[r], 0.f);
}

// ---------------------------------------------------------------------------
// Fused GRU cell.
// xs = x@k + b0 ; hs = h@rk + b1 ; z=sig(xz+hz), r=sig(xr+hr),
// cand=tanh(xh+r*hh) ; out = z*h + (1-z)*cand
// Tiling: BM=32 batch x BN=64 gate cols, Ktile=16, 6 accum sets per cell.
// ---------------------------------------------------------------------------
__global__ __launch_bounds__(256) void gru_kernel(
    const float* __restrict__ x, int xs_stride,
    const float* __restrict__ h, int hs_stride,
    const float* __restrict__ kmat, const float* __restrict__ rkmat,
    const float* __restrict__ bias,
    float* __restrict__ out, int out_stride,
    const float* __restrict__ xin,   // may be null
    float* __restrict__ cout)        // may be null
{
    __shared__ float sX[32][17];
    __shared__ float sH[32][17];
    __shared__ float sW[6][16][64];

    int tid = threadIdx.x;
    int bm0 = blockIdx.x * 32;
    int jn0 = blockIdx.y * 64;
    int tx = tid & 15;        // 16 col-groups of 4
    int ty = tid >> 4;        // 16 -> 2 rows each
    int r0 = ty * 2;

    float acc[2][6][4];
    #pragma unroll
    for (int r = 0; r < 2; r++)
        #pragma unroll
        for (int m = 0; m < 6; m++)
            #pragma unroll
            for (int j = 0; j < 4; j++)
                acc[r][m][j] = 0.f;

    for (int kt0 = 0; kt0 < HID; kt0 += 16) {
        // stage x/h tiles
        for (int idx = tid; idx < 32 * 16; idx += 256) {
            int r = idx >> 4, kk = idx & 15;
            sX[r][kk] = x[(bm0 + r) * xs_stride + kt0 + kk];
            sH[r][kk] = h[(bm0 + r) * hs_stride + kt0 + kk];
        }
        // stage weight tiles: 6 slices (k:z,r,h ; rk:z,r,h) of [16 x 64]
        for (int idx = tid; idx < 6 * 16 * 64; idx += 256) {
            int m = idx >> 10;
            int rem = idx & 1023;
            int kk = rem >> 6, jj = rem & 63;
            const float* src = (m < 3) ? kmat : rkmat;
            int p = (m < 3) ? m : (m - 3);
            sW[m][kk][jj] = src[(kt0 + kk) * (3 * HID) + jn0 + p * HID + jj];
        }
        __syncthreads();

        #pragma unroll
        for (int kk = 0; kk < 16; kk++) {
            float xv0 = sX[r0][kk],     xv1 = sX[r0 + 1][kk];
            float hv0 = sH[r0][kk],     hv1 = sH[r0 + 1][kk];
            #pragma unroll
            for (int m = 0; m < 6; m++) {
                float4 w = *(const float4*)&sW[m][kk][tx * 4];
                float a0 = (m < 3) ? xv0 : hv0;
                float a1 = (m < 3) ? xv1 : hv1;
                acc[0][m][0] = fmaf(a0, w.x, acc[0][m][0]);
                acc[0][m][1] = fmaf(a0, w.y, acc[0][m][1]);
                acc[0][m][2] = fmaf(a0, w.z, acc[0][m][2]);
                acc[0][m][3] = fmaf(a0, w.w, acc[0][m][3]);
                acc[1][m][0] = fmaf(a1, w.x, acc[1][m][0]);
                acc[1][m][1] = fmaf(a1, w.y, acc[1][m][1]);
                acc[1][m][2] = fmaf(a1, w.z, acc[1][m][2]);
                acc[1][m][3] = fmaf(a1, w.w, acc[1][m][3]);
            }
        }
        __syncthreads();
    }

    // epilogue: gate math
    #pragma unroll
    for (int r = 0; r < 2; r++) {
        int row = bm0 + r0 + r;
        #pragma unroll
        for (int jj = 0; jj < 4; jj++) {
            int col = jn0 + tx * 4 + jj;
            float xz = acc[r][0][jj] + bias[col];
            float xr = acc[r][1][jj] + bias[HID + col];
            float xh = acc[r][2][jj] + bias[2 * HID + col];
            float hz = acc[r][3][jj] + bias[3 * HID + col];
            float hr = acc[r][4][jj] + bias[4 * HID + col];
            float hh = acc[r][5][jj] + bias[5 * HID + col];
            float z  = 1.f / (1.f + expf(-(xz + hz)));
            float rg = 1.f / (1.f + expf(-(xr + hr)));
            float cand = tanhf(xh + rg * hh);
            float hv = h[row * hs_stride + col];
            float o  = z * hv + (1.f - z) * cand;
            out[row * out_stride + col] = o;
            if (cout)
                cout[row * HID + col] = o + xin[row * HID + col];
        }
    }
}

// ---------------------------------------------------------------------------
// Tail: grouped conv (KT=5 taps, 2 channel-groups of 8->5) + pw(10x10) + BN +
// relu, plus tanh(grouped_linear(c, w_out)) and transpose-write of coefs.
// Grid: (96 f, 16 b-chunks), block 256 (one thread per b).
// ---------------------------------------------------------------------------
__global__ __launch_bounds__(256) void tail_kernel(
    const float* __restrict__ buf, const float* __restrict__ c0,
    const float* __restrict__ c,
    const float* __restrict__ w_out, const float* __restrict__ conv_w,
    const float* __restrict__ pw_w,
    const float* __restrict__ bn_gamma, const float* __restrict__ bn_beta,
    const float* __restrict__ bn_mean, const float* __restrict__ bn_var,
    float* __restrict__ coefs)
{
    __shared__ float s_cw[KT * 8 * OC];   // 400
    __shared__ float s_pw[OC * OC];       // 100
    __shared__ float s_scale[OC], s_shift[OC];
    __shared__ float s_wo[32 * OC];       // 320 (this f's w_out slice)

    int f = blockIdx.x;
    int tid = threadIdx.x;
    int b = blockIdx.y * 256 + tid;
    int g = f / 12;                 // group of this f's 10 outputs
    int o0 = (f * 10) % 120;        // within-group column base

    for (int idx = tid; idx < KT * 8 * OC; idx += 256) s_cw[idx] = conv_w[idx];
    for (int idx = tid; idx < OC * OC; idx += 256)     s_pw[idx] = pw_w[idx];
    if (tid < OC) {
        float inv = rsqrtf(bn_var[tid] + 1e-3f);
        float sc = inv * bn_gamma[tid];
        s_scale[tid] = sc;
        s_shift[tid] = bn_beta[tid] - bn_mean[tid] * sc;
    }
    for (int idx = tid; idx < 32 * OC; idx += 256) {
        int i = idx / OC, o = idx % OC;
        s_wo[idx] = w_out[g * (32 * 120) + i * 120 + o0 + o];
    }
    __syncthreads();

    // load x[b, t, f, :] for t=0..4 (t=4 is c0)
    float xr[KT][CHAN];
    const float4* bb = (const float4*)(buf + (size_t)b * (4 * FREQ * CHAN) + f * CHAN);
    #pragma unroll
    for (int t = 0; t < 4; t++) {
        #pragma unroll
        for (int q = 0; q < 4; q++) {
            float4 v = bb[t * (FREQ * CHAN / 4) + q];
            xr[t][q*4+0] = v.x; xr[t][q*4+1] = v.y; xr[t][q*4+2] = v.z; xr[t][q*4+3] = v.w;
        }
    }
    {
        const float4* cc = (const float4*)(c0 + (size_t)b * (FREQ * CHAN) + f * CHAN);
        #pragma unroll
        for (int q = 0; q < 4; q++) {
            float4 v = cc[q];
            xr[4][q*4+0] = v.x; xr[4][q*4+1] = v.y; xr[4][q*4+2] = v.z; xr[4][q*4+3] = v.w;
        }
    }

    // grouped conv: y[oc] = sum_t sum_i x[t][(oc/5)*8+i] * cw[t][i][oc]
    float y[OC];
    #pragma unroll
    for (int o = 0; o < OC; o++) y[o] = 0.f;
    #pragma unroll
    for (int t = 0; t < KT; t++)
        #pragma unroll
        for (int g2 = 0; g2 < 2; g2++)
            #pragma unroll
            for (int i = 0; i < 8; i++) {
                float xv = xr[t][g2 * 8 + i];
                #pragma unroll
                for (int o5 = 0; o5 < 5; o5++)
                    y[g2 * 5 + o5] = fmaf(xv, s_cw[t * 80 + i * OC + g2 * 5 + o5], y[g2 * 5 + o5]);
            }

    // pointwise + BN + relu
    float c0o[OC];
    #pragma unroll
    for (int o = 0; o < OC; o++) {
        float a = 0.f;
        #pragma unroll
        for (int k = 0; k < OC; k++) a = fmaf(y[k], s_pw[k * OC + o], a);
        c0o[o] = fmaxf(a * s_scale[o] + s_shift[o], 0.f);
    }

    // grouped out-projection on c
    float cr[32];
    {
        const float4* cp = (const float4*)(c + (size_t)b * HID + g * 32);
        #pragma unroll
        for (int q = 0; q < 8; q++) {
            float4 v = cp[q];
            cr[q*4+0] = v.x; cr[q*4+1] = v.y; cr[q*4+2] = v.z; cr[q*4+3] = v.w;
        }
    }
    float* cf = coefs + (size_t)b * 960 + f * 2;
    #pragma unroll
    for (int oc = 0; oc < OC; oc++) {
        float a = 0.f;
        #pragma unroll
        for (int i = 0; i < 32; i++) a = fmaf(cr[i], s_wo[i * OC + oc], a);
        float v = tanhf(a) + c0o[oc];
        cf[(oc >> 1) * 192 + (oc & 1)] = v;
    }
}

// ---------------------------------------------------------------------------
// alpha[b] = sigmoid(dot(c[b], fc_a_w) + fc_a_b)
// ---------------------------------------------------------------------------
__global__ __launch_bounds__(256) void alpha_kernel(
    const float* __restrict__ c, const float* __restrict__ faw,
    const float* __restrict__ fab, float* __restrict__ alpha)
{
    int b = blockIdx.x * 8 + (threadIdx.x >> 5);
    int lane = threadIdx.x & 31;
    float s = 0.f;
    #pragma unroll
    for (int k = 0; k < 8; k++)
        s = fmaf(c[(size_t)b * HID + k * 32 + lane], faw[k * 32 + lane], s);
    #pragma unroll
    for (int off = 16; off; off >>= 1)
        s += __shfl_xor_sync(0xFFFFFFFFu, s, off);
    if (lane == 0)
        alpha[b] = 1.f / (1.f + expf(-(s + fab[0])));
}

// ---------------------------------------------------------------------------
// new_buf[:, t] = (t<3) ? buf[:, t+1] : c0    (float4 copy)
// ---------------------------------------------------------------------------
__global__ __launch_bounds__(256) void buf_kernel(
    const float* __restrict__ buf, const float* __restrict__ c0,
    float* __restrict__ nb)
{
    int idx = blockIdx.x * 256 + threadIdx.x;           // float4 units
    const int total = N_BUF / 4;                        // 6,291,456
    if (idx >= total) return;
    int b = idx / 1536;
    int rem = idx - b * 1536;
    int t = rem / 384;
    int r = rem - t * 384;
    float4 v;
    if (t < 3) v = ((const float4*)buf)[(size_t)b * 1536 + (t + 1) * 384 + r];
    else       v = ((const float4*)c0)[(size_t)b * 384 + r];
    ((float4*)nb)[idx] = v;
}

// ---------------------------------------------------------------------------
extern "C" void kernel_launch(void* const* d_in, const int* in_sizes, int n_in,
                              void* d_out, int out_size)
{
    const float* emb      = (const float*)d_in[0];
    const float* c0       = (const float*)d_in[1];
    const float* state    = (const float*)d_in[2];
    const float* convbuf  = (const float*)d_in[3];
    const float* w_in     = (const float*)d_in[4];
    const float* k0       = (const float*)d_in[5];
    const float* rk0      = (const float*)d_in[6];
    const float* b0       = (const float*)d_in[7];
    const float* k1       = (const float*)d_in[8];
    const float* rk1      = (const float*)d_in[9];
    const float* b1       = (const float*)d_in[10];
    const float* w_out    = (const float*)d_in[11];
    const float* faw      = (const float*)d_in[12];
    const float* fab      = (const float*)d_in[13];
    const float* conv_w   = (const float*)d_in[14];
    const float* pw_w     = (const float*)d_in[15];
    const float* bn_gamma = (const float*)d_in[16];
    const float* bn_beta  = (const float*)d_in[17];
    const float* bn_mean  = (const float*)d_in[18];
    const float* bn_var   = (const float*)d_in[19];

    float* out = (float*)d_out;
    float* xin; float* cbuf;
    cudaGetSymbolAddress((void**)&xin,  g_xin);
    cudaGetSymbolAddress((void**)&cbuf, g_c);

    // 1) x_in
    xin_kernel<<<BATCH / 8, 256>>>(emb, w_in, xin);

    // 2) GRU0: out0 -> new_state[:, :256]
    gru_kernel<<<dim3(BATCH / 32, 4), 256>>>(
        xin, HID, state, 2 * HID, k0, rk0, b0,
        out + OFF_STATE, 2 * HID, nullptr, nullptr);

    // 3) GRU1: out1 -> new_state[:, 256:], c = out1 + x_in -> scratch
    gru_kernel<<<dim3(BATCH / 32, 4), 256>>>(
        out + OFF_STATE, 2 * HID, state + HID, 2 * HID, k1, rk1, b1,
        out + OFF_STATE + HID, 2 * HID, xin, cbuf);

    // 4) conv/pw/bn/relu + grouped out proj + coefs
    tail_kernel<<<dim3(FREQ, BATCH / 256), 256>>>(
        convbuf, c0, cbuf, w_out, conv_w, pw_w,
        bn_gamma, bn_beta, bn_mean, bn_var, out + OFF_COEFS);

    // 5) alpha
    alpha_kernel<<<BATCH / 8, 256>>>(cbuf, faw, fab, out + OFF_ALPHA);

    // 6) new_buf shifted copy
    buf_kernel<<<(N_BUF / 4 + 255) / 256, 256>>>(convbuf, c0, out + OFF_BUF);
}

// round 2
// speedup vs baseline: 2.6318x; 2.6318x over previous
#include <cuda_runtime.h>
#include <cuda_bf16.h>
#include <math.h>
#include <stdint.h>

// Problem constants
#define BATCH 4096
#define EMB 256
#define HID 256
#define FREQ 96
#define CHAN 16
#define OC 10
#define KT 5

// Output slab offsets (floats): coefs, alpha, new_state, new_buf
#define OFF_COEFS 0
#define N_COEFS   (BATCH * 5 * 96 * 2)
#define OFF_ALPHA (N_COEFS)
#define N_ALPHA   (BATCH)
#define OFF_STATE (OFF_ALPHA + N_ALPHA)
#define N_STATE   (BATCH * 2 * HID)
#define OFF_BUF   (OFF_STATE + N_STATE)
#define N_BUF     (BATCH * 4 * FREQ * CHAN)

// Scratch
__device__ float g_xin[BATCH * HID];
__device__ float g_c[BATCH * HID];

__device__ __forceinline__ uint32_t f2tf32(float v) {
    uint32_t u;
    asm("cvt.rna.tf32.f32 %0, %1;" : "=r"(u) : "f"(v));
    return u;
}

#define MMA_TF32(d, a, b) \
  asm volatile("mma.sync.aligned.m16n8k8.row.col.f32.tf32.tf32.f32 " \
      "{%0,%1,%2,%3}, {%4,%5,%6,%7}, {%8,%9}, {%0,%1,%2,%3};" \
      : "+f"((d)[0]), "+f"((d)[1]), "+f"((d)[2]), "+f"((d)[3]) \
      : "r"((a)[0]), "r"((a)[1]), "r"((a)[2]), "r"((a)[3]), \
        "r"((b)[0]), "r"((b)[1]))

// ---------------------------------------------------------------------------
// x_in = relu(grouped_linear(emb, w_in))
// ---------------------------------------------------------------------------
__global__ __launch_bounds__(256) void xin_kernel(
    const float* __restrict__ emb, const float* __restrict__ w_in,
    float* __restrict__ xout)
{
    __shared__ float sE[8][EMB];
    int b0 = blockIdx.x * 8;
    int tid = threadIdx.x;
    for (int idx = tid; idx < 8 * EMB; idx += 256) {
        int r = idx >> 8, col = idx & 255;
        sE[r][col] = emb[(b0 + r) * EMB + col];
    }
    __syncthreads();
    int j = tid;
    int g = j >> 5, jo = j & 31;
    float acc[8] = {0.f,0.f,0.f,0.f,0.f,0.f,0.f,0.f};
    const float* w = w_in + g * (32 * 32) + jo;
    #pragma unroll 8
    for (int i = 0; i < 32; i++) {
        float wv = w[i * 32];
        #pragma unroll
        for (int r = 0; r < 8; r++)
            acc[r] = fmaf(sE[r][(g << 5) + i], wv, acc[r]);
    }
    #pragma unroll
    for (int r = 0; r < 8; r++)
        xout[(b0 + r) * HID + j] = fmaxf(acc[r], 0.f);
}

// ---------------------------------------------------------------------------
// Fused GRU cell on tensor cores (tf32 mma.sync m16n8k8).
// 4 accumulator sets: (xz+hz), (xr+hr), xh, hh.
// CTA tile: 128 rows x 32 gate cols. 8 warps = 4m x 2n, warp tile 32x16.
// ---------------------------------------------------------------------------
#define KTILE 16
#define SXS 20   // smem row stride (floats); (20*r + c) mod 32 conflict-free frag loads

__global__ __launch_bounds__(256, 2) void gru_mma_kernel(
    const float* __restrict__ x, int xs_stride,
    const float* __restrict__ h, int hs_stride,
    const float* __restrict__ kmat, const float* __restrict__ rkmat,
    const float* __restrict__ bias,
    float* __restrict__ out, int out_stride,
    const float* __restrict__ xin,   // may be null
    float* __restrict__ cout)        // may be null
{
    __shared__ uint32_t sX[128][SXS];
    __shared__ uint32_t sH[128][SXS];
    __shared__ uint32_t sW[6][32][SXS];

    int tid = threadIdx.x;
    int lane = tid & 31;
    int wid = tid >> 5;
    int warp_m = wid & 3;       // 0..3 -> m offset warp_m*32
    int warp_n = wid >> 2;      // 0..1 -> n offset warp_n*16
    int bm0 = blockIdx.x * 128;
    int bn0 = blockIdx.y * 32;
    int g4 = lane >> 2;         // groupID
    int t4 = lane & 3;          // threadID_in_group

    float acc[4][2][2][4];
    #pragma unroll
    for (int s = 0; s < 4; s++)
        #pragma unroll
        for (int mi = 0; mi < 2; mi++)
            #pragma unroll
            for (int ni = 0; ni < 2; ni++)
                #pragma unroll
                for (int j = 0; j < 4; j++)
                    acc[s][mi][ni][j] = 0.f;

    for (int kt0 = 0; kt0 < HID; kt0 += KTILE) {
        // stage X/H tiles (128x16), coalesced, convert to tf32
        for (int idx = tid; idx < 128 * KTILE; idx += 256) {
            int r = idx >> 4, c = idx & 15;
            sX[r][c] = f2tf32(x[(size_t)(bm0 + r) * xs_stride + kt0 + c]);
            sH[r][c] = f2tf32(h[(size_t)(bm0 + r) * hs_stride + kt0 + c]);
        }
        // stage 6 weight tiles [16k x 32n], stored transposed sW[m][n][k]
        for (int idx = tid; idx < 6 * KTILE * 32; idx += 256) {
            int m = idx / (KTILE * 32);
            int rem = idx % (KTILE * 32);
            int kk = rem >> 5, nn = rem & 31;
            const float* src = (m < 3) ? kmat : rkmat;
            int p = (m < 3) ? m : (m - 3);
            sW[m][nn][kk] = f2tf32(src[(size_t)(kt0 + kk) * (3 * HID) + p * HID + bn0 + nn]);
        }
        __syncthreads();

        #pragma unroll
        for (int ks = 0; ks < KTILE; ks += 8) {
            uint32_t ax[2][4], ah[2][4];
            #pragma unroll
            for (int mi = 0; mi < 2; mi++) {
                int r = warp_m * 32 + mi * 16 + g4;
                ax[mi][0] = sX[r][ks + t4];
                ax[mi][1] = sX[r + 8][ks + t4];
                ax[mi][2] = sX[r][ks + t4 + 4];
                ax[mi][3] = sX[r + 8][ks + t4 + 4];
                ah[mi][0] = sH[r][ks + t4];
                ah[mi][1] = sH[r + 8][ks + t4];
                ah[mi][2] = sH[r][ks + t4 + 4];
                ah[mi][3] = sH[r + 8][ks + t4 + 4];
            }
            // m: 0=kz 1=kr 2=kh 3=rkz 4=rkr 5=rkh -> sets 0,1,2,0,1,3
            #pragma unroll
            for (int m = 0; m < 6; m++) {
                const int set = (m == 0 || m == 3) ? 0 : (m == 1 || m == 4) ? 1 : (m == 2) ? 2 : 3;
                uint32_t bf[2][2];
                #pragma unroll
                for (int ni = 0; ni < 2; ni++) {
                    int n = warp_n * 16 + ni * 8 + g4;
                    bf[ni][0] = sW[m][n][ks + t4];
                    bf[ni][1] = sW[m][n][ks + t4 + 4];
                }
                #pragma unroll
                for (int mi = 0; mi < 2; mi++)
                    #pragma unroll
                    for (int ni = 0; ni < 2; ni++) {
                        if (m < 3) { MMA_TF32(acc[set][mi][ni], ax[mi], bf[ni]); }
                        else       { MMA_TF32(acc[set][mi][ni], ah[mi], bf[ni]); }
                    }
            }
        }
        __syncthreads();
    }

    // epilogue: gate math
    #pragma unroll
    for (int mi = 0; mi < 2; mi++) {
        #pragma unroll
        for (int ni = 0; ni < 2; ni++) {
            int colg = bn0 + warp_n * 16 + ni * 8 + 2 * t4;
            #pragma unroll
            for (int half = 0; half < 2; half++) {
                int row = bm0 + warp_m * 32 + mi * 16 + g4 + half * 8;
                float2 hv = *(const float2*)&h[(size_t)row * hs_stride + colg];
                float o2[2];
                #pragma unroll
                for (int j = 0; j < 2; j++) {
                    int col = colg + j;
                    int ri = half * 2 + j;
                    float az  = acc[0][mi][ni][ri] + bias[col]        + bias[768 + col];
                    float ar  = acc[1][mi][ni][ri] + bias[256 + col]  + bias[1024 + col];
                    float axh = acc[2][mi][ni][ri] + bias[512 + col];
                    float ahh = acc[3][mi][ni][ri] + bias[1280 + col];
                    float z  = 1.f / (1.f + __expf(-az));
                    float rg = 1.f / (1.f + __expf(-ar));
                    float cand = tanhf(axh + rg * ahh);
                    float hvv = j ? hv.y : hv.x;
                    o2[j] = z * hvv + (1.f - z) * cand;
                }
                *(float2*)&out[(size_t)row * out_stride + colg] = make_float2(o2[0], o2[1]);
                if (cout) {
                    float2 xi = *(const float2*)&xin[(size_t)row * HID + colg];
                    *(float2*)&cout[(size_t)row * HID + colg] =
                        make_float2(o2[0] + xi.x, o2[1] + xi.y);
                }
            }
        }
    }
}

// ---------------------------------------------------------------------------
// Tail: grouped conv + pw + BN + relu + grouped out proj + tanh + coefs write,
// AND fused new_buf shifted copy (streams taps, no big register array).
// Grid: (96 f, 16 b-chunks), block 256.
// ---------------------------------------------------------------------------
__global__ __launch_bounds__(256) void tail_kernel(
    const float* __restrict__ buf, const float* __restrict__ c0,
    const float* __restrict__ c,
    const float* __restrict__ w_out, const float* __restrict__ conv_w,
    const float* __restrict__ pw_w,
    const float* __restrict__ bn_gamma, const float* __restrict__ bn_beta,
    const float* __restrict__ bn_mean, const float* __restrict__ bn_var,
    float* __restrict__ coefs, float* __restrict__ new_buf)
{
    __shared__ float s_cw[KT * 8 * OC];   // 400
    __shared__ float s_pw[OC * OC];       // 100
    __shared__ float s_scale[OC], s_shift[OC];
    __shared__ float s_wo[32 * OC];       // 320

    int f = blockIdx.x;
    int tid = threadIdx.x;
    int b = blockIdx.y * 256 + tid;
    int g = f / 12;
    int o0 = (f * 10) % 120;

    for (int idx = tid; idx < KT * 8 * OC; idx += 256) s_cw[idx] = conv_w[idx];
    for (int idx = tid; idx < OC * OC; idx += 256)     s_pw[idx] = pw_w[idx];
    if (tid < OC) {
        float inv = rsqrtf(bn_var[tid] + 1e-3f);
        float sc = inv * bn_gamma[tid];
        s_scale[tid] = sc;
        s_shift[tid] = bn_beta[tid] - bn_mean[tid] * sc;
    }
    for (int idx = tid; idx < 32 * OC; idx += 256) {
        int i = idx / OC, o = idx % OC;
        s_wo[idx] = w_out[g * (32 * 120) + i * 120 + o0 + o];
    }
    __syncthreads();

    float y[OC];
    #pragma unroll
    for (int o = 0; o < OC; o++) y[o] = 0.f;

    // stream taps t=0..4 (t<4 from buf, t=4 from c0); write new_buf[t-1]=x[t]
    #pragma unroll
    for (int t = 0; t < KT; t++) {
        const float4* src = (t < 4)
            ? (const float4*)(buf + (size_t)b * (4 * FREQ * CHAN) + t * (FREQ * CHAN) + f * CHAN)
            : (const float4*)(c0 + (size_t)b * (FREQ * CHAN) + f * CHAN);
        float v[16];
        #pragma unroll
        for (int q = 0; q < 4; q++) {
            float4 w4 = src[q];
            v[q*4+0] = w4.x; v[q*4+1] = w4.y; v[q*4+2] = w4.z; v[q*4+3] = w4.w;
        }
        if (t >= 1) {
            float4* dst = (float4*)(new_buf + (size_t)b * (4 * FREQ * CHAN)
                                    + (t - 1) * (FREQ * CHAN) + f * CHAN);
            #pragma unroll
            for (int q = 0; q < 4; q++)
                dst[q] = make_float4(v[q*4+0], v[q*4+1], v[q*4+2], v[q*4+3]);
        }
        #pragma unroll
        for (int g2 = 0; g2 < 2; g2++)
            #pragma unroll
            for (int i = 0; i < 8; i++) {
                float xv = v[g2 * 8 + i];
                #pragma unroll
                for (int o5 = 0; o5 < 5; o5++)
                    y[g2 * 5 + o5] = fmaf(xv, s_cw[t * 80 + i * OC + g2 * 5 + o5],
                                          y[g2 * 5 + o5]);
            }
    }

    // pointwise + BN + relu
    float c0o[OC];
    #pragma unroll
    for (int o = 0; o < OC; o++) {
        float a = 0.f;
        #pragma unroll
        for (int k = 0; k < OC; k++) a = fmaf(y[k], s_pw[k * OC + o], a);
        c0o[o] = fmaxf(a * s_scale[o] + s_shift[o], 0.f);
    }

    // grouped out-projection on c + tanh + add + transposed coefs write
    float cr[32];
    {
        const float4* cp = (const float4*)(c + (size_t)b * HID + g * 32);
        #pragma unroll
        for (int q = 0; q < 8; q++) {
            float4 vv = cp[q];
            cr[q*4+0] = vv.x; cr[q*4+1] = vv.y; cr[q*4+2] = vv.z; cr[q*4+3] = vv.w;
        }
    }
    float* cf = coefs + (size_t)b * 960 + f * 2;
    #pragma unroll
    for (int oc = 0; oc < OC; oc++) {
        float a = 0.f;
        #pragma unroll
        for (int i = 0; i < 32; i++) a = fmaf(cr[i], s_wo[i * OC + oc], a);
        float vv = tanhf(a) + c0o[oc];
        cf[(oc >> 1) * 192 + (oc & 1)] = vv;
    }
}

// ---------------------------------------------------------------------------
__global__ __launch_bounds__(256) void alpha_kernel(
    const float* __restrict__ c, const float* __restrict__ faw,
    const float* __restrict__ fab, float* __restrict__ alpha)
{
    int b = blockIdx.x * 8 + (threadIdx.x >> 5);
    int lane = threadIdx.x & 31;
    float s = 0.f;
    #pragma unroll
    for (int k = 0; k < 8; k++)
        s = fmaf(c[(size_t)b * HID + k * 32 + lane], faw[k * 32 + lane], s);
    #pragma unroll
    for (int off = 16; off; off >>= 1)
        s += __shfl_xor_sync(0xFFFFFFFFu, s, off);
    if (lane == 0)
        alpha[b] = 1.f / (1.f + expf(-(s + fab[0])));
}

// ---------------------------------------------------------------------------
extern "C" void kernel_launch(void* const* d_in, const int* in_sizes, int n_in,
                              void* d_out, int out_size)
{
    const float* emb      = (const float*)d_in[0];
    const float* c0       = (const float*)d_in[1];
    const float* state    = (const float*)d_in[2];
    const float* convbuf  = (const float*)d_in[3];
    const float* w_in     = (const float*)d_in[4];
    const float* k0       = (const float*)d_in[5];
    const float* rk0      = (const float*)d_in[6];
    const float* b0       = (const float*)d_in[7];
    const float* k1       = (const float*)d_in[8];
    const float* rk1      = (const float*)d_in[9];
    const float* b1       = (const float*)d_in[10];
    const float* w_out    = (const float*)d_in[11];
    const float* faw      = (const float*)d_in[12];
    const float* fab      = (const float*)d_in[13];
    const float* conv_w   = (const float*)d_in[14];
    const float* pw_w     = (const float*)d_in[15];
    const float* bn_gamma = (const float*)d_in[16];
    const float* bn_beta  = (const float*)d_in[17];
    const float* bn_mean  = (const float*)d_in[18];
    const float* bn_var   = (const float*)d_in[19];

    float* out = (float*)d_out;
    float* xin; float* cbuf;
    cudaGetSymbolAddress((void**)&xin,  g_xin);
    cudaGetSymbolAddress((void**)&cbuf, g_c);

    // 1) x_in
    xin_kernel<<<BATCH / 8, 256>>>(emb, w_in, xin);

    // 2) GRU0: out0 -> new_state[:, :256]
    gru_mma_kernel<<<dim3(BATCH / 128, HID / 32), 256>>>(
        xin, HID, state, 2 * HID, k0, rk0, b0,
        out + OFF_STATE, 2 * HID, nullptr, nullptr);

    // 3) GRU1: out1 -> new_state[:, 256:], c -> scratch
    gru_mma_kernel<<<dim3(BATCH / 128, HID / 32), 256>>>(
        out + OFF_STATE, 2 * HID, state + HID, 2 * HID, k1, rk1, b1,
        out + OFF_STATE + HID, 2 * HID, xin, cbuf);

    // 4) tail (conv/pw/bn/relu + proj + coefs) with fused new_buf copy
    tail_kernel<<<dim3(FREQ, BATCH / 256), 256>>>(
        convbuf, c0, cbuf, w_out, conv_w, pw_w,
        bn_gamma, bn_beta, bn_mean, bn_var,
        out + OFF_COEFS, out + OFF_BUF);

    // 5) alpha
    alpha_kernel<<<BATCH / 8, 256>>>(cbuf, faw, fab, out + OFF_ALPHA);
}

// round 3
// speedup vs baseline: 4.3233x; 1.6427x over previous
#include <cuda_runtime.h>
#include <cuda_bf16.h>
#include <math.h>
#include <stdint.h>

#define BATCH 4096
#define EMB 256
#define HID 256
#define FREQ 96
#define CHAN 16
#define OC 10
#define KT 5

#define OFF_COEFS 0
#define N_COEFS   (BATCH * 5 * 96 * 2)
#define OFF_ALPHA (N_COEFS)
#define N_ALPHA   (BATCH)
#define OFF_STATE (OFF_ALPHA + N_ALPHA)
#define N_STATE   (BATCH * 2 * HID)
#define OFF_BUF   (OFF_STATE + N_STATE)
#define N_BUF     (BATCH * 4 * FREQ * CHAN)

__device__ float g_xin[BATCH * HID];
__device__ float g_c[BATCH * HID];

#define MMA_TF32(d, a, b) \
  asm volatile("mma.sync.aligned.m16n8k8.row.col.f32.tf32.tf32.f32 " \
      "{%0,%1,%2,%3}, {%4,%5,%6,%7}, {%8,%9}, {%0,%1,%2,%3};" \
      : "+f"((d)[0]), "+f"((d)[1]), "+f"((d)[2]), "+f"((d)[3]) \
      : "r"((a)[0]), "r"((a)[1]), "r"((a)[2]), "r"((a)[3]), \
        "r"((b)[0]), "r"((b)[1]))

#define CP16(dst_u32, src_ptr) \
  asm volatile("cp.async.ca.shared.global [%0], [%1], 16;" :: "r"(dst_u32), "l"(src_ptr))
#define CP_COMMIT() asm volatile("cp.async.commit_group;")
#define CP_WAIT1()  asm volatile("cp.async.wait_group 1;")

// ---------------------------------------------------------------------------
// x_in = relu(grouped_linear(emb, w_in))
// ---------------------------------------------------------------------------
__global__ __launch_bounds__(256) void xin_kernel(
    const float* __restrict__ emb, const float* __restrict__ w_in,
    float* __restrict__ xout)
{
    __shared__ float sE[8][EMB];
    int b0 = blockIdx.x * 8;
    int tid = threadIdx.x;
    for (int idx = tid; idx < 8 * EMB; idx += 256) {
        int r = idx >> 8, col = idx & 255;
        sE[r][col] = emb[(b0 + r) * EMB + col];
    }
    __syncthreads();
    int j = tid;
    int g = j >> 5, jo = j & 31;
    float acc[8] = {0.f,0.f,0.f,0.f,0.f,0.f,0.f,0.f};
    const float* w = w_in + g * (32 * 32) + jo;
    #pragma unroll 8
    for (int i = 0; i < 32; i++) {
        float wv = w[i * 32];
        #pragma unroll
        for (int r = 0; r < 8; r++)
            acc[r] = fmaf(sE[r][(g << 5) + i], wv, acc[r]);
    }
    #pragma unroll
    for (int r = 0; r < 8; r++)
        xout[(b0 + r) * HID + j] = fmaxf(acc[r], 0.f);
}

// ---------------------------------------------------------------------------
// Fused GRU cell, tf32 mma.sync m16n8k8, cp.async double-buffered pipeline.
// CTA tile 128 x 32. 8 warps = 4m x 2n (warp tile 32x16). KTILE=16, 2 stages.
// smem per stage (floats): X 128x20, H 128x20, W 6x16x40  => 8960 floats.
// ---------------------------------------------------------------------------
#define GRU_STAGE_F 8960

__global__ __launch_bounds__(256) void gru_mma_kernel(
    const float* __restrict__ x, int xs_stride,
    const float* __restrict__ h, int hs_stride,
    const float* __restrict__ kmat, const float* __restrict__ rkmat,
    const float* __restrict__ bias,
    float* __restrict__ out, int out_stride,
    const float* __restrict__ xin,
    float* __restrict__ cout)
{
    extern __shared__ float smem_dyn[];
    uint32_t smem_u = (uint32_t)__cvta_generic_to_shared(smem_dyn);

    int tid = threadIdx.x;
    int lane = tid & 31;
    int wid = tid >> 5;
    int warp_m = wid & 3;
    int warp_n = wid >> 2;
    int bm0 = blockIdx.x * 128;
    int bn0 = blockIdx.y * 32;
    int g4 = lane >> 2;
    int t4 = lane & 3;

    float acc[4][2][2][4];
    #pragma unroll
    for (int s = 0; s < 4; s++)
        #pragma unroll
        for (int mi = 0; mi < 2; mi++)
            #pragma unroll
            for (int ni = 0; ni < 2; ni++)
                #pragma unroll
                for (int j = 0; j < 4; j++)
                    acc[s][mi][ni][j] = 0.f;

    // stage tile kt0 into buffer p
    auto stage = [&](int p, int kt0) {
        uint32_t su = smem_u + (uint32_t)(p * GRU_STAGE_F) * 4u;
        #pragma unroll
        for (int it = 0; it < 7; it++) {
            int idx = tid + it * 256;           // 0..1791
            if (idx < 512) {
                int row = idx >> 2, q = idx & 3;
                const float* src = x + (size_t)(bm0 + row) * xs_stride + kt0 + q * 4;
                CP16(su + (uint32_t)(row * 20 + q * 4) * 4u, src);
            } else if (idx < 1024) {
                int j = idx - 512;
                int row = j >> 2, q = j & 3;
                const float* src = h + (size_t)(bm0 + row) * hs_stride + kt0 + q * 4;
                CP16(su + (uint32_t)(2560 + row * 20 + q * 4) * 4u, src);
            } else {
                int w = idx - 1024;             // 0..767
                int m = w >> 7;
                int rem = w & 127;
                int kk = rem >> 3, q = rem & 7;
                const float* sw = (m < 3) ? kmat : rkmat;
                int pp = (m < 3) ? m : (m - 3);
                const float* src = sw + (size_t)(kt0 + kk) * 768 + pp * 256 + bn0 + q * 4;
                CP16(su + (uint32_t)(5120 + (m * 16 + kk) * 40 + q * 4) * 4u, src);
            }
        }
    };

    stage(0, 0);
    CP_COMMIT();

    for (int t = 0; t < 16; t++) {
        if (t < 15) stage((t + 1) & 1, (t + 1) * 16);
        CP_COMMIT();
        CP_WAIT1();
        __syncthreads();

        const float* bufp = smem_dyn + (t & 1) * GRU_STAGE_F;
        const float* sXf = bufp;
        const float* sHf = bufp + 2560;
        const float* sWf = bufp + 5120;

        #pragma unroll
        for (int ks = 0; ks < 16; ks += 8) {
            uint32_t ax[2][4], ah[2][4];
            #pragma unroll
            for (int mi = 0; mi < 2; mi++) {
                int r = warp_m * 32 + mi * 16 + g4;
                ax[mi][0] = __float_as_uint(sXf[r * 20 + ks + t4]);
                ax[mi][1] = __float_as_uint(sXf[(r + 8) * 20 + ks + t4]);
                ax[mi][2] = __float_as_uint(sXf[r * 20 + ks + t4 + 4]);
                ax[mi][3] = __float_as_uint(sXf[(r + 8) * 20 + ks + t4 + 4]);
                ah[mi][0] = __float_as_uint(sHf[r * 20 + ks + t4]);
                ah[mi][1] = __float_as_uint(sHf[(r + 8) * 20 + ks + t4]);
                ah[mi][2] = __float_as_uint(sHf[r * 20 + ks + t4 + 4]);
                ah[mi][3] = __float_as_uint(sHf[(r + 8) * 20 + ks + t4 + 4]);
            }
            #pragma unroll
            for (int m = 0; m < 6; m++) {
                const int set = (m == 0 || m == 3) ? 0 : (m == 1 || m == 4) ? 1 : (m == 2) ? 2 : 3;
                uint32_t bf[2][2];
                #pragma unroll
                for (int ni = 0; ni < 2; ni++) {
                    int n = warp_n * 16 + ni * 8 + g4;
                    bf[ni][0] = __float_as_uint(sWf[(m * 16 + ks + t4) * 40 + n]);
                    bf[ni][1] = __float_as_uint(sWf[(m * 16 + ks + t4 + 4) * 40 + n]);
                }
                #pragma unroll
                for (int mi = 0; mi < 2; mi++)
                    #pragma unroll
                    for (int ni = 0; ni < 2; ni++) {
                        if (m < 3) { MMA_TF32(acc[set][mi][ni], ax[mi], bf[ni]); }
                        else       { MMA_TF32(acc[set][mi][ni], ah[mi], bf[ni]); }
                    }
            }
        }
        __syncthreads();
    }

    // epilogue: gate math
    #pragma unroll
    for (int mi = 0; mi < 2; mi++) {
        #pragma unroll
        for (int ni = 0; ni < 2; ni++) {
            int colg = bn0 + warp_n * 16 + ni * 8 + 2 * t4;
            #pragma unroll
            for (int half = 0; half < 2; half++) {
                int row = bm0 + warp_m * 32 + mi * 16 + g4 + half * 8;
                float2 hv = *(const float2*)&h[(size_t)row * hs_stride + colg];
                float o2[2];
                #pragma unroll
                for (int j = 0; j < 2; j++) {
                    int col = colg + j;
                    int ri = half * 2 + j;
                    float az  = acc[0][mi][ni][ri] + bias[col]       + bias[768 + col];
                    float ar  = acc[1][mi][ni][ri] + bias[256 + col] + bias[1024 + col];
                    float axh = acc[2][mi][ni][ri] + bias[512 + col];
                    float ahh = acc[3][mi][ni][ri] + bias[1280 + col];
                    float z  = 1.f / (1.f + __expf(-az));
                    float rg = 1.f / (1.f + __expf(-ar));
                    float cand = tanhf(axh + rg * ahh);
                    float hvv = j ? hv.y : hv.x;
                    o2[j] = z * hvv + (1.f - z) * cand;
                }
                *(float2*)&out[(size_t)row * out_stride + colg] = make_float2(o2[0], o2[1]);
                if (cout) {
                    float2 xi = *(const float2*)&xin[(size_t)row * HID + colg];
                    *(float2*)&cout[(size_t)row * HID + colg] =
                        make_float2(o2[0] + xi.x, o2[1] + xi.y);
                }
            }
        }
    }
}

// ---------------------------------------------------------------------------
// Tail: coalesced mapping. Block = 32 b x 8 f (256 threads).
// Warps span contiguous f -> fully coalesced buf/c0/new_buf accesses.
// ---------------------------------------------------------------------------
__global__ __launch_bounds__(256, 2) void tail_kernel(
    const float* __restrict__ buf, const float* __restrict__ c0,
    const float* __restrict__ c,
    const float* __restrict__ w_out, const float* __restrict__ conv_w,
    const float* __restrict__ pw_w,
    const float* __restrict__ bn_gamma, const float* __restrict__ bn_beta,
    const float* __restrict__ bn_mean, const float* __restrict__ bn_var,
    float* __restrict__ coefs, float* __restrict__ new_buf)
{
    __shared__ float s_cw[KT * 8 * OC];   // 400
    __shared__ float s_pw[OC * OC];       // 100
    __shared__ float s_scale[OC], s_shift[OC];
    __shared__ float s_wo[8][325];        // stride 325: 5*fi mod 32 distinct

    int tid = threadIdx.x;
    int f0 = blockIdx.x * 8;
    int bi = tid >> 3;
    int fi = tid & 7;
    int f = f0 + fi;
    int b = blockIdx.y * 32 + bi;
    int g = f / 12;
    int o0 = (f * 10) % 120;

    for (int idx = tid; idx < KT * 8 * OC; idx += 256) s_cw[idx] = conv_w[idx];
    for (int idx = tid; idx < OC * OC; idx += 256)     s_pw[idx] = pw_w[idx];
    if (tid < OC) {
        float inv = rsqrtf(bn_var[tid] + 1e-3f);
        float sc = inv * bn_gamma[tid];
        s_scale[tid] = sc;
        s_shift[tid] = bn_beta[tid] - bn_mean[tid] * sc;
    }
    for (int idx = tid; idx < 8 * 320; idx += 256) {
        int ff = idx / 320;
        int rem = idx - ff * 320;          // i*10 + o
        int i = rem / 10, o = rem - i * 10;
        int fg = f0 + ff;
        int gg = fg / 12;
        int oo0 = (fg * 10) % 120;
        s_wo[ff][rem] = w_out[gg * 3840 + i * 120 + oo0 + o];
    }
    __syncthreads();

    float y[OC];
    #pragma unroll
    for (int o = 0; o < OC; o++) y[o] = 0.f;

    // stream taps; t<4 from buf, t=4 from c0; new_buf[t-1] = x[t]
    #pragma unroll
    for (int t = 0; t < KT; t++) {
        const float4* src = (t < 4)
            ? (const float4*)(buf + (size_t)b * (4 * FREQ * CHAN) + t * (FREQ * CHAN) + f * CHAN)
            : (const float4*)(c0 + (size_t)b * (FREQ * CHAN) + f * CHAN);
        float v[16];
        #pragma unroll
        for (int q = 0; q < 4; q++) {
            float4 w4 = src[q];
            v[q*4+0] = w4.x; v[q*4+1] = w4.y; v[q*4+2] = w4.z; v[q*4+3] = w4.w;
        }
        if (t >= 1) {
            float4* dst = (float4*)(new_buf + (size_t)b * (4 * FREQ * CHAN)
                                    + (t - 1) * (FREQ * CHAN) + f * CHAN);
            #pragma unroll
            for (int q = 0; q < 4; q++)
                dst[q] = make_float4(v[q*4+0], v[q*4+1], v[q*4+2], v[q*4+3]);
        }
        #pragma unroll
        for (int g2 = 0; g2 < 2; g2++)
            #pragma unroll
            for (int i = 0; i < 8; i++) {
                float xv = v[g2 * 8 + i];
                #pragma unroll
                for (int o5 = 0; o5 < 5; o5++)
                    y[g2 * 5 + o5] = fmaf(xv, s_cw[t * 80 + i * OC + g2 * 5 + o5],
                                          y[g2 * 5 + o5]);
            }
    }

    // pointwise + BN + relu
    float c0o[OC];
    #pragma unroll
    for (int o = 0; o < OC; o++) {
        float a = 0.f;
        #pragma unroll
        for (int k = 0; k < OC; k++) a = fmaf(y[k], s_pw[k * OC + o], a);
        c0o[o] = fmaxf(a * s_scale[o] + s_shift[o], 0.f);
    }

    // grouped out-projection on c + tanh + add + transposed coefs write
    float cr[32];
    {
        const float4* cp = (const float4*)(c + (size_t)b * HID + g * 32);
        #pragma unroll
        for (int q = 0; q < 8; q++) {
            float4 vv = cp[q];
            cr[q*4+0] = vv.x; cr[q*4+1] = vv.y; cr[q*4+2] = vv.z; cr[q*4+3] = vv.w;
        }
    }
    float* cf = coefs + (size_t)b * 960 + f * 2;
    #pragma unroll
    for (int oc = 0; oc < OC; oc++) {
        float a = 0.f;
        #pragma unroll
        for (int i = 0; i < 32; i++) a = fmaf(cr[i], s_wo[fi][i * 10 + oc], a);
        float vv = tanhf(a) + c0o[oc];
        cf[(oc >> 1) * 192 + (oc & 1)] = vv;
    }
}

// ---------------------------------------------------------------------------
__global__ __launch_bounds__(256) void alpha_kernel(
    const float* __restrict__ c, const float* __restrict__ faw,
    const float* __restrict__ fab, float* __restrict__ alpha)
{
    int b = blockIdx.x * 8 + (threadIdx.x >> 5);
    int lane = threadIdx.x & 31;
    float s = 0.f;
    #pragma unroll
    for (int k = 0; k < 8; k++)
        s = fmaf(c[(size_t)b * HID + k * 32 + lane], faw[k * 32 + lane], s);
    #pragma unroll
    for (int off = 16; off; off >>= 1)
        s += __shfl_xor_sync(0xFFFFFFFFu, s, off);
    if (lane == 0)
        alpha[b] = 1.f / (1.f + expf(-(s + fab[0])));
}

// ---------------------------------------------------------------------------
extern "C" void kernel_launch(void* const* d_in, const int* in_sizes, int n_in,
                              void* d_out, int out_size)
{
    const float* emb      = (const float*)d_in[0];
    const float* c0       = (const float*)d_in[1];
    const float* state    = (const float*)d_in[2];
    const float* convbuf  = (const float*)d_in[3];
    const float* w_in     = (const float*)d_in[4];
    const float* k0       = (const float*)d_in[5];
    const float* rk0      = (const float*)d_in[6];
    const float* b0       = (const float*)d_in[7];
    const float* k1       = (const float*)d_in[8];
    const float* rk1      = (const float*)d_in[9];
    const float* b1       = (const float*)d_in[10];
    const float* w_out    = (const float*)d_in[11];
    const float* faw      = (const float*)d_in[12];
    const float* fab      = (const float*)d_in[13];
    const float* conv_w   = (const float*)d_in[14];
    const float* pw_w     = (const float*)d_in[15];
    const float* bn_gamma = (const float*)d_in[16];
    const float* bn_beta  = (const float*)d_in[17];
    const float* bn_mean  = (const float*)d_in[18];
    const float* bn_var   = (const float*)d_in[19];

    float* out = (float*)d_out;
    float* xin; float* cbuf;
    cudaGetSymbolAddress((void**)&xin,  g_xin);
    cudaGetSymbolAddress((void**)&cbuf, g_c);

    const int gru_smem = 2 * GRU_STAGE_F * 4;   // 71,680 B
    cudaFuncSetAttribute(gru_mma_kernel,
        cudaFuncAttributeMaxDynamicSharedMemorySize, gru_smem);

    // 1) x_in
    xin_kernel<<<BATCH / 8, 256>>>(emb, w_in, xin);

    // 2) GRU0
    gru_mma_kernel<<<dim3(BATCH / 128, HID / 32), 256, gru_smem>>>(
        xin, HID, state, 2 * HID, k0, rk0, b0,
        out + OFF_STATE, 2 * HID, nullptr, nullptr);

    // 3) GRU1 (+ c = out1 + x_in)
    gru_mma_kernel<<<dim3(BATCH / 128, HID / 32), 256, gru_smem>>>(
        out + OFF_STATE, 2 * HID, state + HID, 2 * HID, k1, rk1, b1,
        out + OFF_STATE + HID, 2 * HID, xin, cbuf);

    // 4) tail (conv/pw/bn/relu + proj + coefs + new_buf), coalesced mapping
    tail_kernel<<<dim3(FREQ / 8, BATCH / 32), 256>>>(
        convbuf, c0, cbuf, w_out, conv_w, pw_w,
        bn_gamma, bn_beta, bn_mean, bn_var,
        out + OFF_COEFS, out + OFF_BUF);

    // 5) alpha
    alpha_kernel<<<BATCH / 8, 256>>>(cbuf, faw, fab, out + OFF_ALPHA);
}